// round 7
// baseline (speedup 1.0000x reference)
#include <cuda_runtime.h>
#include <cstdint>

#define HF 64
#define WF 64
#define CC 256
#define NB 4
#define KK 2048

// NHWC-transposed feature map scratch: [N][H][W][C] = 4*64*64*256 floats = 16 MB
__device__ float g_nhwc[NB * HF * WF * CC];

// ---------------------------------------------------------------------------
// Kernel 1: NCHW -> NHWC transpose via 32x32 smem tiles, coalesced both sides.
// ---------------------------------------------------------------------------
__global__ void transpose_nchw_nhwc(const float* __restrict__ in) {
    __shared__ float tile[32][33];
    const int n  = blockIdx.z;
    const int c0 = blockIdx.y * 32;
    const int s0 = blockIdx.x * 32;

    const float* inp = in + (size_t)n * CC * (HF * WF);
#pragma unroll
    for (int i = 0; i < 32; i += 8) {
        tile[threadIdx.y + i][threadIdx.x] =
            inp[(size_t)(c0 + threadIdx.y + i) * (HF * WF) + s0 + threadIdx.x];
    }
    __syncthreads();

    float* outp = g_nhwc + (size_t)n * (HF * WF) * CC;
#pragma unroll
    for (int i = 0; i < 32; i += 8) {
        outp[(size_t)(s0 + threadIdx.y + i) * CC + c0 + threadIdx.x] =
            tile[threadIdx.x][threadIdx.y + i];
    }
}

__device__ __forceinline__ float4 fmax4(float4 a, float4 b) {
    a.x = fmaxf(a.x, b.x);
    a.y = fmaxf(a.y, b.y);
    a.z = fmaxf(a.z, b.z);
    a.w = fmaxf(a.w, b.w);
    return a;
}

// ---------------------------------------------------------------------------
// Kernel 2: RoI max pool — exact R4 structure (best measured: 125 us),
// with the only change being min-blocks 6 -> 7 (regs 40 -> <=36, 56 warps/SM).
//   grid  = (2 channel-halves, 2048 rois), block = 256 threads
//   thread t: channel group cg = t&31 (4 channels via float4),
//             bin slice   sl = t>>5 (warp-uniform bin index)
// ---------------------------------------------------------------------------
__global__ __launch_bounds__(256, 7)
void roipool_kernel(const float* __restrict__ rois, float* __restrict__ out) {
    __shared__ float sres[128 * 49];

    const int k    = blockIdx.y;
    const int half = blockIdx.x;
    const int tid  = threadIdx.x;
    const int cg   = tid & 31;   // channel group: channels half*128 + 4*cg + {0..3}
    const int sl   = tid >> 5;   // bin slice 0..7 (one warp per slice)

    const float* r = rois + (size_t)k * 5;
    const int b   = (int)r[0];
    const int rsw = __float2int_rn(r[1] * 0.0625f);  // round-half-even == jnp.round
    const int rsh = __float2int_rn(r[2] * 0.0625f);
    const int rew = __float2int_rn(r[3] * 0.0625f);
    const int reh = __float2int_rn(r[4] * 0.0625f);
    const int roi_w = max(rew - rsw + 1, 1);
    const int roi_h = max(reh - rsh + 1, 1);

    // Reciprocal-multiply division matches the reference's XLA lowering
    // (verified R2: rel_err == 0). Do not change to exact divide.
    const float RCP7  = 1.0f / 7.0f;
    const float bin_h = (float)roi_h * RCP7;
    const float bin_w = (float)roi_w * RCP7;

    // float4 view: cell (h,w), channel-group g at index (h*WF+w)*64 + g
    const float4* base =
        (const float4*)(g_nhwc + (size_t)b * (HF * WF) * CC) + (half * 32 + cg);

    const float NEG_INF = __int_as_float(0xff800000);

    int bi            = (49 * sl) >> 3;        // 6,6,6,6,6,6,6,7 bins/slice
    const int bi_end  = (49 * (sl + 1)) >> 3;

    for (; bi < bi_end; ++bi) {
        const int ph = bi / 7;                 // const-div -> mul/shift
        const int pw = bi - ph * 7;

        int hstart = (int)floorf((float)ph * bin_h) + rsh;
        int hend   = (int)ceilf((float)(ph + 1) * bin_h) + rsh;
        hstart = min(max(hstart, 0), HF);
        hend   = min(max(hend, 0), HF);

        int wstart = (int)floorf((float)pw * bin_w) + rsw;
        int wend   = (int)ceilf((float)(pw + 1) * bin_w) + rsw;
        wstart = min(max(wstart, 0), WF);
        wend   = min(max(wend, 0), WF);

        float4 m0 = make_float4(NEG_INF, NEG_INF, NEG_INF, NEG_INF);
        float4 m1 = m0;
        const int wc = wend - wstart;

        const float4* rowp = base + (size_t)(hstart * WF + wstart) * 64;
        for (int h = hstart; h < hend; ++h) {
            int w = 0;
#pragma unroll 2
            for (; w + 2 <= wc; w += 2) {
                float4 a = __ldg(rowp + (size_t)w * 64);
                float4 c = __ldg(rowp + (size_t)(w + 1) * 64);
                m0 = fmax4(m0, a);
                m1 = fmax4(m1, c);
            }
            if (w < wc) m0 = fmax4(m0, __ldg(rowp + (size_t)w * 64));
            rowp += (size_t)WF * 64;
        }
        float4 m = fmax4(m0, m1);

        if (!((hstart < hend) && (wstart < wend)))
            m = make_float4(0.f, 0.f, 0.f, 0.f);

        const int cbase = 4 * cg;
        sres[(cbase + 0) * 49 + bi] = m.x;
        sres[(cbase + 1) * 49 + bi] = m.y;
        sres[(cbase + 2) * 49 + bi] = m.z;
        sres[(cbase + 3) * 49 + bi] = m.w;
    }
    __syncthreads();

    // Contiguous coalesced flush: this block owns output span
    // [k*12544 + half*6272, +6272) = 1568 float4.
    float4* outv = (float4*)(out + (size_t)k * (CC * 49) + (size_t)half * (128 * 49));
    const float4* sv = (const float4*)sres;
#pragma unroll
    for (int i = 0; i < 6; ++i) {
        int t = tid + i * 256;
        outv[t] = sv[t];
    }
    if (tid < 1568 - 6 * 256) {
        int t = tid + 6 * 256;
        outv[t] = sv[t];
    }
}

extern "C" void kernel_launch(void* const* d_in, const int* in_sizes, int n_in,
                              void* d_out, int out_size) {
    const float* input = (const float*)d_in[0];   // [4,256,64,64] fp32
    const float* rois  = (const float*)d_in[1];   // [2048,5] fp32
    float* out = (float*)d_out;                   // [2048,256,7,7] fp32

    dim3 tgrid((HF * WF) / 32, CC / 32, NB);      // (128, 8, 4)
    transpose_nchw_nhwc<<<tgrid, dim3(32, 8)>>>(input);

    roipool_kernel<<<dim3(2, KK), 256>>>(rois, out);
}

// round 8
// speedup vs baseline: 2.0539x; 2.0539x over previous
#include <cuda_runtime.h>
#include <cstdint>

#define HF 64
#define WF 64
#define CC 256
#define NB 4
#define KK 2048

// NHWC feature map: [N][H][W][C] = 16 MB
__device__ float g_nhwc[NB * HF * WF * CC];
// Row-pair max pyramid: H1[n][h2][w][c] = max(nhwc[n][2h2][w][c], nhwc[n][2h2+1][w][c]) = 8 MB
__device__ float g_h1[NB * (HF / 2) * WF * CC];

// ---------------------------------------------------------------------------
// Kernel 1: NCHW -> NHWC transpose via 32x32 smem tiles, coalesced both sides.
// ---------------------------------------------------------------------------
__global__ void transpose_nchw_nhwc(const float* __restrict__ in) {
    __shared__ float tile[32][33];
    const int n  = blockIdx.z;
    const int c0 = blockIdx.y * 32;
    const int s0 = blockIdx.x * 32;

    const float* inp = in + (size_t)n * CC * (HF * WF);
#pragma unroll
    for (int i = 0; i < 32; i += 8) {
        tile[threadIdx.y + i][threadIdx.x] =
            inp[(size_t)(c0 + threadIdx.y + i) * (HF * WF) + s0 + threadIdx.x];
    }
    __syncthreads();

    float* outp = g_nhwc + (size_t)n * (HF * WF) * CC;
#pragma unroll
    for (int i = 0; i < 32; i += 8) {
        outp[(size_t)(s0 + threadIdx.y + i) * CC + c0 + threadIdx.x] =
            tile[threadIdx.x][threadIdx.y + i];
    }
}

__device__ __forceinline__ float4 fmax4(float4 a, float4 b) {
    a.x = fmaxf(a.x, b.x);
    a.y = fmaxf(a.y, b.y);
    a.z = fmaxf(a.z, b.z);
    a.w = fmaxf(a.w, b.w);
    return a;
}

// ---------------------------------------------------------------------------
// Kernel 1b: build row-pair max pyramid H1 (NHWC layout, half height).
// 2.1M float4 outputs; thread i -> one float4. Fully coalesced.
// ---------------------------------------------------------------------------
__global__ void build_h1() {
    const size_t i = (size_t)blockIdx.x * blockDim.x + threadIdx.x;  // float4 index
    const size_t total = (size_t)NB * (HF / 2) * WF * (CC / 4);
    if (i >= total) return;
    // i = ((n*(HF/2) + h2)*WF + w)*(CC/4) + g ; source rows 2h2, 2h2+1 differ by
    // WF*CC floats = WF*(CC/4) float4.
    const size_t g_and_w = i % ((size_t)WF * (CC / 4));
    const size_t nh2     = i / ((size_t)WF * (CC / 4));
    const size_t n       = nh2 / (HF / 2);
    const size_t h2      = nh2 % (HF / 2);
    const float4* src = (const float4*)g_nhwc +
        ((n * HF + 2 * h2) * (size_t)WF * (CC / 4)) + g_and_w;
    float4 a = src[0];
    float4 b = src[(size_t)WF * (CC / 4)];
    ((float4*)g_h1)[i] = fmax4(a, b);
}

// ---------------------------------------------------------------------------
// Kernel 2: RoI max pool — R4 structure; h-loop decomposed into
// odd lead row (orig) + aligned row-pairs (H1) + tail row (orig).
//   grid = (2 channel-halves, 2048 rois), block = 256 threads
//   cg = tid&31 (4 channels, float4), sl = tid>>5 (warp-uniform bin slice)
// ---------------------------------------------------------------------------
__global__ __launch_bounds__(256, 6)
void roipool_kernel(const float* __restrict__ rois, float* __restrict__ out) {
    __shared__ float sres[128 * 49];

    const int k    = blockIdx.y;
    const int half = blockIdx.x;
    const int tid  = threadIdx.x;
    const int cg   = tid & 31;
    const int sl   = tid >> 5;

    const float* r = rois + (size_t)k * 5;
    const int b   = (int)r[0];
    const int rsw = __float2int_rn(r[1] * 0.0625f);  // round-half-even == jnp.round
    const int rsh = __float2int_rn(r[2] * 0.0625f);
    const int rew = __float2int_rn(r[3] * 0.0625f);
    const int reh = __float2int_rn(r[4] * 0.0625f);
    const int roi_w = max(rew - rsw + 1, 1);
    const int roi_h = max(reh - rsh + 1, 1);

    // Reciprocal-multiply division matches the reference's XLA lowering
    // (verified R2: rel_err == 0). Do not change to exact divide.
    const float RCP7  = 1.0f / 7.0f;
    const float bin_h = (float)roi_h * RCP7;
    const float bin_w = (float)roi_w * RCP7;

    const int coff = half * 32 + cg;
    const float4* base  = (const float4*)(g_nhwc + (size_t)b * (HF * WF) * CC) + coff;
    const float4* base1 = (const float4*)(g_h1 + (size_t)b * ((HF / 2) * WF) * CC) + coff;

    const float NEG_INF = __int_as_float(0xff800000);

    int bi           = (49 * sl) >> 3;        // 6,6,6,6,6,6,6,7 bins/slice
    const int bi_end = (49 * (sl + 1)) >> 3;

    for (; bi < bi_end; ++bi) {
        const int ph = bi / 7;
        const int pw = bi - ph * 7;

        int hstart = (int)floorf((float)ph * bin_h) + rsh;
        int hend   = (int)ceilf((float)(ph + 1) * bin_h) + rsh;
        hstart = min(max(hstart, 0), HF);
        hend   = min(max(hend, 0), HF);

        int wstart = (int)floorf((float)pw * bin_w) + rsw;
        int wend   = (int)ceilf((float)(pw + 1) * bin_w) + rsw;
        wstart = min(max(wstart, 0), WF);
        wend   = min(max(wend, 0), WF);

        float4 m0 = make_float4(NEG_INF, NEG_INF, NEG_INF, NEG_INF);
        float4 m1 = m0;
        const int wc = wend - wstart;

        int h = hstart;
        // odd lead row from orig
        if ((h & 1) && h < hend) {
            const float4* rowp = base + (size_t)(h * WF + wstart) * 64;
            int w = 0;
#pragma unroll 2
            for (; w + 2 <= wc; w += 2) {
                float4 a = __ldg(rowp + (size_t)w * 64);
                float4 c = __ldg(rowp + (size_t)(w + 1) * 64);
                m0 = fmax4(m0, a);
                m1 = fmax4(m1, c);
            }
            if (w < wc) m0 = fmax4(m0, __ldg(rowp + (size_t)w * 64));
            ++h;
        }
        // aligned pairs from H1
        {
            const float4* rowp = base1 + (size_t)((h >> 1) * WF + wstart) * 64;
            for (; h + 2 <= hend; h += 2) {
                int w = 0;
#pragma unroll 2
                for (; w + 2 <= wc; w += 2) {
                    float4 a = __ldg(rowp + (size_t)w * 64);
                    float4 c = __ldg(rowp + (size_t)(w + 1) * 64);
                    m0 = fmax4(m0, a);
                    m1 = fmax4(m1, c);
                }
                if (w < wc) m0 = fmax4(m0, __ldg(rowp + (size_t)w * 64));
                rowp += (size_t)WF * 64;
            }
        }
        // tail row from orig
        if (h < hend) {
            const float4* rowp = base + (size_t)(h * WF + wstart) * 64;
            int w = 0;
#pragma unroll 2
            for (; w + 2 <= wc; w += 2) {
                float4 a = __ldg(rowp + (size_t)w * 64);
                float4 c = __ldg(rowp + (size_t)(w + 1) * 64);
                m0 = fmax4(m0, a);
                m1 = fmax4(m1, c);
            }
            if (w < wc) m0 = fmax4(m0, __ldg(rowp + (size_t)w * 64));
        }

        float4 m = fmax4(m0, m1);
        if (!((hstart < hend) && (wstart < wend)))
            m = make_float4(0.f, 0.f, 0.f, 0.f);

        const int cbase = 4 * cg;
        sres[(cbase + 0) * 49 + bi] = m.x;
        sres[(cbase + 1) * 49 + bi] = m.y;
        sres[(cbase + 2) * 49 + bi] = m.z;
        sres[(cbase + 3) * 49 + bi] = m.w;
    }
    __syncthreads();

    // Contiguous coalesced flush: block owns output span
    // [k*12544 + half*6272, +6272) = 1568 float4.
    float4* outv = (float4*)(out + (size_t)k * (CC * 49) + (size_t)half * (128 * 49));
    const float4* sv = (const float4*)sres;
#pragma unroll
    for (int i = 0; i < 6; ++i) {
        int t = tid + i * 256;
        outv[t] = sv[t];
    }
    if (tid < 1568 - 6 * 256) {
        int t = tid + 6 * 256;
        outv[t] = sv[t];
    }
}

extern "C" void kernel_launch(void* const* d_in, const int* in_sizes, int n_in,
                              void* d_out, int out_size) {
    const float* input = (const float*)d_in[0];   // [4,256,64,64] fp32
    const float* rois  = (const float*)d_in[1];   // [2048,5] fp32
    float* out = (float*)d_out;                   // [2048,256,7,7] fp32

    dim3 tgrid((HF * WF) / 32, CC / 32, NB);      // (128, 8, 4)
    transpose_nchw_nhwc<<<tgrid, dim3(32, 8)>>>(input);

    const int h1_total = NB * (HF / 2) * WF * (CC / 4);   // 524288 float4
    build_h1<<<(h1_total + 255) / 256, 256>>>();

    roipool_kernel<<<dim3(2, KK), 256>>>(rois, out);
}